// round 4
// baseline (speedup 1.0000x reference)
#include <cuda_runtime.h>
#include <math.h>

#define N_ROWS 16384
#define K_CB   4096
#define D_DIM  256

__device__ float g_xn[N_ROWS * D_DIM];
__device__ float g_cbn[K_CB * D_DIM];
__device__ float g_loss_partial[N_ROWS];
__device__ int   g_counts[K_CB];

// ---------------------------------------------------------------------------
__device__ __forceinline__ float block_reduce_sum256(float v, float* sh8) {
    const int t = threadIdx.x;
    #pragma unroll
    for (int o = 16; o > 0; o >>= 1) v += __shfl_xor_sync(0xffffffffu, v, o);
    const int warp = t >> 5, lane = t & 31;
    if (lane == 0) sh8[warp] = v;
    __syncthreads();
    if (warp == 0) {
        float x = (lane < 8) ? sh8[lane] : 0.0f;
        #pragma unroll
        for (int o = 4; o > 0; o >>= 1) x += __shfl_xor_sync(0xffffffffu, x, o);
        if (lane == 0) sh8[0] = x;
    }
    __syncthreads();
    float r = sh8[0];
    __syncthreads();
    return r;
}

// ---------------------------------------------------------------------------
__global__ void normalize_cb_kernel(const float* __restrict__ in) {
    __shared__ float sh[8];
    const int row = blockIdx.x, t = threadIdx.x;
    const float v = in[row * D_DIM + t];
    const float ss = block_reduce_sum256(v * v, sh);
    const float norm = fmaxf(sqrtf(ss), 1e-12f);
    g_cbn[row * D_DIM + t] = v / norm;
    if (t == 0) g_counts[row] = 0;
}

__global__ void normalize_x_kernel(const float* __restrict__ in) {
    __shared__ float sh[8];
    const int row = blockIdx.x, t = threadIdx.x;
    const float v = in[row * D_DIM + t];
    const float ss = block_reduce_sum256(v * v, sh);
    const float norm = fmaxf(sqrtf(ss), 1e-12f);
    g_xn[row * D_DIM + t] = v / norm;
}

// ---------------------------------------------------------------------------
// GEMM: logits[n,k] = 20*dot - 20. Scalar stores into probs (4B-aligned only).
// ---------------------------------------------------------------------------
__global__ __launch_bounds__(256, 2)
void gemm_logits_kernel(float* __restrict__ C) {
    __shared__ float As[16][128];
    __shared__ float Bs[16][128];
    const int t  = threadIdx.x;
    const int tx = t & 15;
    const int ty = t >> 4;
    const int m0 = blockIdx.y << 7;
    const int n0 = blockIdx.x << 7;

    float acc[8][8];
    #pragma unroll
    for (int i = 0; i < 8; i++)
        #pragma unroll
        for (int j = 0; j < 8; j++) acc[i][j] = 0.0f;

    const int lrow = t >> 1;
    const int lcol = (t & 1) << 3;
    const float* Aptr = g_xn  + (m0 + lrow) * D_DIM + lcol;
    const float* Bptr = g_cbn + (n0 + lrow) * D_DIM + lcol;

    for (int d0 = 0; d0 < D_DIM; d0 += 16) {
        const float4 a0 = *(const float4*)(Aptr + d0);
        const float4 a1 = *(const float4*)(Aptr + d0 + 4);
        const float4 b0 = *(const float4*)(Bptr + d0);
        const float4 b1 = *(const float4*)(Bptr + d0 + 4);
        if (d0) __syncthreads();
        As[lcol + 0][lrow] = a0.x; As[lcol + 1][lrow] = a0.y;
        As[lcol + 2][lrow] = a0.z; As[lcol + 3][lrow] = a0.w;
        As[lcol + 4][lrow] = a1.x; As[lcol + 5][lrow] = a1.y;
        As[lcol + 6][lrow] = a1.z; As[lcol + 7][lrow] = a1.w;
        Bs[lcol + 0][lrow] = b0.x; Bs[lcol + 1][lrow] = b0.y;
        Bs[lcol + 2][lrow] = b0.z; Bs[lcol + 3][lrow] = b0.w;
        Bs[lcol + 4][lrow] = b1.x; Bs[lcol + 5][lrow] = b1.y;
        Bs[lcol + 6][lrow] = b1.z; Bs[lcol + 7][lrow] = b1.w;
        __syncthreads();

        #pragma unroll
        for (int dd = 0; dd < 16; dd++) {
            const float4 av0 = *(const float4*)&As[dd][(ty << 2)];
            const float4 av1 = *(const float4*)&As[dd][64 + (ty << 2)];
            const float4 bv0 = *(const float4*)&Bs[dd][(tx << 2)];
            const float4 bv1 = *(const float4*)&Bs[dd][64 + (tx << 2)];
            const float ar[8] = {av0.x, av0.y, av0.z, av0.w, av1.x, av1.y, av1.z, av1.w};
            const float br[8] = {bv0.x, bv0.y, bv0.z, bv0.w, bv1.x, bv1.y, bv1.z, bv1.w};
            #pragma unroll
            for (int i = 0; i < 8; i++)
                #pragma unroll
                for (int j = 0; j < 8; j++)
                    acc[i][j] = fmaf(ar[i], br[j], acc[i][j]);
        }
    }

    #pragma unroll
    for (int i = 0; i < 8; i++) {
        const int mloc = (i < 4) ? ((ty << 2) + i) : (64 + (ty << 2) + (i - 4));
        float* crow = C + (size_t)(m0 + mloc) * K_CB + n0;
        #pragma unroll
        for (int j = 0; j < 4; j++) {
            crow[(tx << 2) + j]      = fmaf(20.0f, acc[i][j],     -20.0f);
            crow[64 + (tx << 2) + j] = fmaf(20.0f, acc[i][j + 4], -20.0f);
        }
    }
}

// ---------------------------------------------------------------------------
// Per-row: softmax, argmin with epsilon-merged tie-break (matches jnp.argmin
// on the reference's fp32 dist grid), gather, loss, histogram, idx.
// ---------------------------------------------------------------------------
__global__ void softmax_row_kernel(float* __restrict__ probs,
                                   float* __restrict__ quant,
                                   float* __restrict__ idx_out) {
    __shared__ float sv[256];
    __shared__ int   si[256];
    __shared__ float xrow[256];
    const int n = blockIdx.x, t = threadIdx.x;
    float* row = probs + (size_t)n * K_CB;

    xrow[t] = g_xn[n * D_DIM + t];

    float lv[16];
    float best = -1e30f;
    #pragma unroll
    for (int i = 0; i < 16; i++) {
        lv[i] = row[t + (i << 8)];
        best = fmaxf(best, lv[i]);
    }
    sv[t] = best;
    __syncthreads();
    #pragma unroll
    for (int s = 128; s > 0; s >>= 1) {
        if (t < s) sv[t] = fmaxf(sv[t], sv[t + s]);
        __syncthreads();
    }
    const float rmax = sv[0];
    __syncthreads();

    // --- candidate rescoring in fp64 (exact dist order for gaps > ~2 ulp) ---
    const float thresh = rmax - 1e-3f;   // dist margin 1e-4 >> GEMM noise
    double bdist = 1e30;
    int    bidx  = 0x7fffffff;
    #pragma unroll
    for (int i = 0; i < 16; i++) {
        if (lv[i] >= thresh) {
            const int k = t + (i << 8);
            const float* cb = g_cbn + (size_t)k * D_DIM;
            double a0 = 0.0, a1 = 0.0, a2 = 0.0, a3 = 0.0;
            for (int d = 0; d < D_DIM; d += 4) {
                a0 += (double)xrow[d]     * (double)cb[d];
                a1 += (double)xrow[d + 1] * (double)cb[d + 1];
                a2 += (double)xrow[d + 2] * (double)cb[d + 2];
                a3 += (double)xrow[d + 3] * (double)cb[d + 3];
            }
            const double dist = 2.0 - 2.0 * ((a0 + a1) + (a2 + a3));
            if (dist < bdist || (dist == bdist && k < bidx)) { bdist = dist; bidx = k; }
        }
    }
    // block-level exact min
    sv[t] = (float)bdist; si[t] = bidx;
    __shared__ double sd[256];
    sd[t] = bdist;
    __syncthreads();
    #pragma unroll
    for (int s = 128; s > 0; s >>= 1) {
        if (t < s) {
            const double ov = sd[t + s]; const int oi = si[t + s];
            if (ov < sd[t] || (ov == sd[t] && oi < si[t])) { sd[t] = ov; si[t] = oi; }
        }
        __syncthreads();
    }
    const double dmin = sd[0];
    __syncthreads();
    // epsilon-merge: among candidates within 4e-7 (≈2-3 fp32 ulp of dist — the
    // band the reference's fp32 matmul cannot resolve), take the LOWEST index
    // (jnp.argmin tie semantics on its fl(2-2*dot) grid).
    int mi = (bdist <= dmin + 4e-7) ? bidx : 0x7fffffff;
    si[t] = mi;
    __syncthreads();
    #pragma unroll
    for (int s = 128; s > 0; s >>= 1) {
        if (t < s) si[t] = min(si[t], si[t + s]);
        __syncthreads();
    }
    const int ridx = si[0];
    __syncthreads();

    // --- softmax (in place) ---
    float ssum = 0.0f;
    #pragma unroll
    for (int i = 0; i < 16; i++) {
        lv[i] = __expf(lv[i] - rmax);
        ssum += lv[i];
    }
    const float tot = block_reduce_sum256(ssum, sv);
    const float inv = 1.0f / tot;
    #pragma unroll
    for (int i = 0; i < 16; i++) row[t + (i << 8)] = lv[i] * inv;

    // --- quantized row + loss partial + histogram + idx ---
    const float xv = xrow[t];
    const float cv = g_cbn[(size_t)ridx * D_DIM + t];
    quant[(size_t)n * D_DIM + t] = xv + (cv - xv);
    const float d = cv - xv;
    const float lp = block_reduce_sum256(d * d, sv);
    if (t == 0) {
        g_loss_partial[n] = lp;
        atomicAdd(&g_counts[ridx], 1);
        idx_out[n] = (float)ridx;
    }
}

// ---------------------------------------------------------------------------
__global__ void finalize_kernel(float* __restrict__ out_loss,
                                float* __restrict__ out_perp) {
    __shared__ float sh[8];
    const int t = threadIdx.x;
    float s = 0.0f;
    for (int i = t; i < N_ROWS; i += 256) s += g_loss_partial[i];
    const float tot = block_reduce_sum256(s, sh);

    float e = 0.0f;
    for (int i = t; i < K_CB; i += 256) {
        const float p = (float)g_counts[i] / (float)N_ROWS;
        e += p * logf(p + 1e-10f);
    }
    const float esum = block_reduce_sum256(e, sh);

    if (t == 0) {
        *out_loss = 0.25f * (tot / (float)((size_t)N_ROWS * D_DIM));
        *out_perp = expf(-esum);
    }
}

// ---------------------------------------------------------------------------
extern "C" void kernel_launch(void* const* d_in, const int* in_sizes, int n_in,
                              void* d_out, int out_size) {
    const float* inputs   = (const float*)d_in[0];
    const float* codebook = (const float*)d_in[1];

    float* out       = (float*)d_out;
    float* out_loss  = out;
    float* out_quant = out + 1;
    float* out_probs = out_quant + (size_t)N_ROWS * D_DIM;
    float* out_perp  = out_probs + (size_t)N_ROWS * K_CB;
    float* out_idx   = out_perp + 1;

    normalize_cb_kernel<<<K_CB, 256>>>(codebook);
    normalize_x_kernel<<<N_ROWS, 256>>>(inputs);

    dim3 grid(K_CB / 128, N_ROWS / 128);
    gemm_logits_kernel<<<grid, 256>>>(out_probs);

    softmax_row_kernel<<<N_ROWS, 256>>>(out_probs, out_quant, out_idx);
    finalize_kernel<<<1, 256>>>(out_loss, out_perp);
}

// round 5
// speedup vs baseline: 1.8706x; 1.8706x over previous
#include <cuda_runtime.h>
#include <math.h>

#define N_ROWS 16384
#define K_CB   4096
#define D_DIM  256

__device__ float g_xn[N_ROWS * D_DIM];
__device__ float g_cbn[K_CB * D_DIM];
__device__ float g_loss_partial[N_ROWS];
__device__ int   g_counts[K_CB];

// ---------------------------------------------------------------------------
// Deterministic block reductions, 256 threads (shuffle + 8-warp combine)
// ---------------------------------------------------------------------------
__device__ __forceinline__ float block_reduce_sum256(float v, float* sh8) {
    const int t = threadIdx.x;
    #pragma unroll
    for (int o = 16; o > 0; o >>= 1) v += __shfl_xor_sync(0xffffffffu, v, o);
    const int warp = t >> 5, lane = t & 31;
    if (lane == 0) sh8[warp] = v;
    __syncthreads();
    if (warp == 0) {
        float x = (lane < 8) ? sh8[lane] : 0.0f;
        #pragma unroll
        for (int o = 4; o > 0; o >>= 1) x += __shfl_xor_sync(0xffffffffu, x, o);
        if (lane == 0) sh8[0] = x;
    }
    __syncthreads();
    float r = sh8[0];
    __syncthreads();
    return r;
}

__device__ __forceinline__ float block_reduce_max256(float v, float* sh8) {
    const int t = threadIdx.x;
    #pragma unroll
    for (int o = 16; o > 0; o >>= 1) v = fmaxf(v, __shfl_xor_sync(0xffffffffu, v, o));
    const int warp = t >> 5, lane = t & 31;
    if (lane == 0) sh8[warp] = v;
    __syncthreads();
    if (warp == 0) {
        float x = (lane < 8) ? sh8[lane] : -1e30f;
        #pragma unroll
        for (int o = 4; o > 0; o >>= 1) x = fmaxf(x, __shfl_xor_sync(0xffffffffu, x, o));
        if (lane == 0) sh8[0] = x;
    }
    __syncthreads();
    float r = sh8[0];
    __syncthreads();
    return r;
}

__device__ __forceinline__ double block_reduce_sum256_d(double v, double* shd8) {
    const int t = threadIdx.x;
    #pragma unroll
    for (int o = 16; o > 0; o >>= 1) v += __shfl_xor_sync(0xffffffffu, v, o);
    const int warp = t >> 5, lane = t & 31;
    if (lane == 0) shd8[warp] = v;
    __syncthreads();
    if (warp == 0) {
        double x = (lane < 8) ? shd8[lane] : 0.0;
        #pragma unroll
        for (int o = 4; o > 0; o >>= 1) x += __shfl_xor_sync(0xffffffffu, x, o);
        if (lane == 0) shd8[0] = x;
    }
    __syncthreads();
    double r = shd8[0];
    __syncthreads();
    return r;
}

// ---------------------------------------------------------------------------
__global__ void normalize_cb_kernel(const float* __restrict__ in) {
    __shared__ float sh[8];
    const int row = blockIdx.x, t = threadIdx.x;
    const float v = in[row * D_DIM + t];
    const float ss = block_reduce_sum256(v * v, sh);
    const float norm = fmaxf(sqrtf(ss), 1e-12f);
    g_cbn[row * D_DIM + t] = v / norm;
    if (t == 0) g_counts[row] = 0;
}

__global__ void normalize_x_kernel(const float* __restrict__ in) {
    __shared__ float sh[8];
    const int row = blockIdx.x, t = threadIdx.x;
    const float v = in[row * D_DIM + t];
    const float ss = block_reduce_sum256(v * v, sh);
    const float norm = fmaxf(sqrtf(ss), 1e-12f);
    g_xn[row * D_DIM + t] = v / norm;
}

// ---------------------------------------------------------------------------
// GEMM: logits[n,k] = 20*dot - 20.  Double-buffered smem pipeline.
// Scalar stores into probs (4B-aligned region only).
// ---------------------------------------------------------------------------
__global__ __launch_bounds__(256, 2)
void gemm_logits_kernel(float* __restrict__ C) {
    __shared__ float As[2][16][128];
    __shared__ float Bs[2][16][128];
    const int t  = threadIdx.x;
    const int tx = t & 15;
    const int ty = t >> 4;
    const int m0 = blockIdx.y << 7;
    const int n0 = blockIdx.x << 7;

    float acc[8][8];
    #pragma unroll
    for (int i = 0; i < 8; i++)
        #pragma unroll
        for (int j = 0; j < 8; j++) acc[i][j] = 0.0f;

    const int lrow = t >> 1;
    const int lcol = (t & 1) << 3;
    const float* Aptr = g_xn  + (m0 + lrow) * D_DIM + lcol;
    const float* Bptr = g_cbn + (n0 + lrow) * D_DIM + lcol;

    float4 a0 = *(const float4*)(Aptr);
    float4 a1 = *(const float4*)(Aptr + 4);
    float4 b0 = *(const float4*)(Bptr);
    float4 b1 = *(const float4*)(Bptr + 4);

    int buf = 0;
    #pragma unroll 1
    for (int kt = 0; kt < 16; kt++) {
        As[buf][lcol + 0][lrow] = a0.x; As[buf][lcol + 1][lrow] = a0.y;
        As[buf][lcol + 2][lrow] = a0.z; As[buf][lcol + 3][lrow] = a0.w;
        As[buf][lcol + 4][lrow] = a1.x; As[buf][lcol + 5][lrow] = a1.y;
        As[buf][lcol + 6][lrow] = a1.z; As[buf][lcol + 7][lrow] = a1.w;
        Bs[buf][lcol + 0][lrow] = b0.x; Bs[buf][lcol + 1][lrow] = b0.y;
        Bs[buf][lcol + 2][lrow] = b0.z; Bs[buf][lcol + 3][lrow] = b0.w;
        Bs[buf][lcol + 4][lrow] = b1.x; Bs[buf][lcol + 5][lrow] = b1.y;
        Bs[buf][lcol + 6][lrow] = b1.z; Bs[buf][lcol + 7][lrow] = b1.w;
        __syncthreads();

        if (kt < 15) {
            const int d0 = (kt + 1) << 4;
            a0 = *(const float4*)(Aptr + d0);
            a1 = *(const float4*)(Aptr + d0 + 4);
            b0 = *(const float4*)(Bptr + d0);
            b1 = *(const float4*)(Bptr + d0 + 4);
        }

        #pragma unroll
        for (int dd = 0; dd < 16; dd++) {
            const float4 av0 = *(const float4*)&As[buf][dd][(ty << 2)];
            const float4 av1 = *(const float4*)&As[buf][dd][64 + (ty << 2)];
            const float4 bv0 = *(const float4*)&Bs[buf][dd][(tx << 2)];
            const float4 bv1 = *(const float4*)&Bs[buf][dd][64 + (tx << 2)];
            const float ar[8] = {av0.x, av0.y, av0.z, av0.w, av1.x, av1.y, av1.z, av1.w};
            const float br[8] = {bv0.x, bv0.y, bv0.z, bv0.w, bv1.x, bv1.y, bv1.z, bv1.w};
            #pragma unroll
            for (int i = 0; i < 8; i++)
                #pragma unroll
                for (int j = 0; j < 8; j++)
                    acc[i][j] = fmaf(ar[i], br[j], acc[i][j]);
        }
        buf ^= 1;
    }

    #pragma unroll
    for (int i = 0; i < 8; i++) {
        const int mloc = (i < 4) ? ((ty << 2) + i) : (64 + (ty << 2) + (i - 4));
        float* crow = C + (size_t)(m0 + mloc) * K_CB + n0;
        #pragma unroll
        for (int j = 0; j < 4; j++) {
            crow[(tx << 2) + j]      = fmaf(20.0f, acc[i][j],     -20.0f);
            crow[64 + (tx << 2) + j] = fmaf(20.0f, acc[i][j + 4], -20.0f);
        }
    }
}

// ---------------------------------------------------------------------------
// Per-row: softmax + argmin (cooperative fp64 rescore of near-max candidates,
// epsilon-merged lowest-index tie-break) + gather + loss + histogram + idx.
// ---------------------------------------------------------------------------
#define MAX_CAND 64

__global__ __launch_bounds__(256)
void softmax_row_kernel(float* __restrict__ probs,
                        float* __restrict__ quant,
                        float* __restrict__ idx_out) {
    __shared__ float  xrow[256];
    __shared__ float  sh8[8];
    __shared__ double shd8[8];
    __shared__ int    cand[MAX_CAND];
    __shared__ double cdist[MAX_CAND];
    __shared__ int    ncand;
    __shared__ int    ridx_sh;

    const int n = blockIdx.x, t = threadIdx.x;
    float* row = probs + (size_t)n * K_CB;

    xrow[t] = g_xn[n * D_DIM + t];
    if (t == 0) ncand = 0;

    float lv[16];
    float best = -1e30f;
    #pragma unroll
    for (int i = 0; i < 16; i++) {
        lv[i] = row[t + (i << 8)];
        best = fmaxf(best, lv[i]);
    }
    __syncthreads();   // xrow + ncand visible
    const float rmax = block_reduce_max256(best, sh8);

    // collect candidates within 1e-3 logit of max (>> fp32 GEMM noise)
    const float thresh = rmax - 1e-3f;
    #pragma unroll
    for (int i = 0; i < 16; i++) {
        if (lv[i] >= thresh) {
            const int p = atomicAdd(&ncand, 1);
            if (p < MAX_CAND) cand[p] = t + (i << 8);
        }
    }
    __syncthreads();
    const int nc = min(ncand, MAX_CAND);

    // cooperative exact fp64 dist for each candidate (fixed reduction tree)
    for (int c = 0; c < nc; c++) {
        const int k = cand[c];
        const double prod = (double)xrow[t] * (double)g_cbn[(size_t)k * D_DIM + t];
        const double s = block_reduce_sum256_d(prod, shd8);
        if (t == 0) cdist[c] = 2.0 - 2.0 * s;
    }
    __syncthreads();

    if (t == 0) {
        double dmin = 1e30;
        for (int c = 0; c < nc; c++) dmin = fmin(dmin, cdist[c]);
        // epsilon-merge (~2-3 fp32 dist ulps): lowest index wins, matching
        // jnp.argmin tie semantics on the reference's fl(2-2*dot) grid.
        int bi = 0x7fffffff;
        for (int c = 0; c < nc; c++)
            if (cdist[c] <= dmin + 4e-7) bi = min(bi, cand[c]);
        ridx_sh = bi;
    }

    // softmax (in place) — barriers inside the reduce also publish ridx_sh
    float ssum = 0.0f;
    #pragma unroll
    for (int i = 0; i < 16; i++) {
        lv[i] = __expf(lv[i] - rmax);
        ssum += lv[i];
    }
    const float tot = block_reduce_sum256(ssum, sh8);
    const float inv = 1.0f / tot;
    #pragma unroll
    for (int i = 0; i < 16; i++) row[t + (i << 8)] = lv[i] * inv;

    const int ridx = ridx_sh;
    const float xv = xrow[t];
    const float cv = g_cbn[(size_t)ridx * D_DIM + t];
    quant[(size_t)n * D_DIM + t] = xv + (cv - xv);
    const float d = cv - xv;
    const float lp = block_reduce_sum256(d * d, sh8);
    if (t == 0) {
        g_loss_partial[n] = lp;
        atomicAdd(&g_counts[ridx], 1);
        idx_out[n] = (float)ridx;
    }
}

// ---------------------------------------------------------------------------
__global__ void finalize_kernel(float* __restrict__ out_loss,
                                float* __restrict__ out_perp) {
    __shared__ float sh[8];
    const int t = threadIdx.x;
    float s = 0.0f;
    for (int i = t; i < N_ROWS; i += 256) s += g_loss_partial[i];
    const float tot = block_reduce_sum256(s, sh);

    float e = 0.0f;
    for (int i = t; i < K_CB; i += 256) {
        const float p = (float)g_counts[i] / (float)N_ROWS;
        e += p * logf(p + 1e-10f);
    }
    const float esum = block_reduce_sum256(e, sh);

    if (t == 0) {
        *out_loss = 0.25f * (tot / (float)((size_t)N_ROWS * D_DIM));
        *out_perp = expf(-esum);
    }
}

// ---------------------------------------------------------------------------
extern "C" void kernel_launch(void* const* d_in, const int* in_sizes, int n_in,
                              void* d_out, int out_size) {
    const float* inputs   = (const float*)d_in[0];
    const float* codebook = (const float*)d_in[1];

    float* out       = (float*)d_out;
    float* out_loss  = out;
    float* out_quant = out + 1;
    float* out_probs = out_quant + (size_t)N_ROWS * D_DIM;
    float* out_perp  = out_probs + (size_t)N_ROWS * K_CB;
    float* out_idx   = out_perp + 1;

    normalize_cb_kernel<<<K_CB, 256>>>(codebook);
    normalize_x_kernel<<<N_ROWS, 256>>>(inputs);

    dim3 grid(K_CB / 128, N_ROWS / 128);
    gemm_logits_kernel<<<grid, 256>>>(out_probs);

    softmax_row_kernel<<<N_ROWS, 256>>>(out_probs, out_quant, out_idx);
    finalize_kernel<<<1, 256>>>(out_loss, out_perp);
}

// round 7
// speedup vs baseline: 2.3220x; 1.2413x over previous
#include <cuda_runtime.h>
#include <cuda_bf16.h>
#include <math.h>
#include <cstdint>

#define N_ROWS 16384
#define K_CB   4096
#define D_DIM  256

__device__ float g_xn[N_ROWS * D_DIM];
__device__ float g_cbn[K_CB * D_DIM];
__device__ __nv_bfloat16 g_xh[N_ROWS * D_DIM];
__device__ __nv_bfloat16 g_xl[N_ROWS * D_DIM];
__device__ __nv_bfloat16 g_cbh[K_CB * D_DIM];
__device__ __nv_bfloat16 g_cbl[K_CB * D_DIM];
__device__ float g_loss_partial[N_ROWS];
__device__ int   g_counts[K_CB];

// ===================== reductions ==========================================
__device__ __forceinline__ float block_reduce_sum256(float v, float* sh8) {
    const int t = threadIdx.x;
    #pragma unroll
    for (int o = 16; o > 0; o >>= 1) v += __shfl_xor_sync(0xffffffffu, v, o);
    const int warp = t >> 5, lane = t & 31;
    if (lane == 0) sh8[warp] = v;
    __syncthreads();
    if (warp == 0) {
        float x = (lane < 8) ? sh8[lane] : 0.0f;
        #pragma unroll
        for (int o = 4; o > 0; o >>= 1) x += __shfl_xor_sync(0xffffffffu, x, o);
        if (lane == 0) sh8[0] = x;
    }
    __syncthreads();
    float r = sh8[0];
    __syncthreads();
    return r;
}
__device__ __forceinline__ float block_reduce_max256(float v, float* sh8) {
    const int t = threadIdx.x;
    #pragma unroll
    for (int o = 16; o > 0; o >>= 1) v = fmaxf(v, __shfl_xor_sync(0xffffffffu, v, o));
    const int warp = t >> 5, lane = t & 31;
    if (lane == 0) sh8[warp] = v;
    __syncthreads();
    if (warp == 0) {
        float x = (lane < 8) ? sh8[lane] : -1e30f;
        #pragma unroll
        for (int o = 4; o > 0; o >>= 1) x = fmaxf(x, __shfl_xor_sync(0xffffffffu, x, o));
        if (lane == 0) sh8[0] = x;
    }
    __syncthreads();
    float r = sh8[0];
    __syncthreads();
    return r;
}
__device__ __forceinline__ double block_reduce_sum256_d(double v, double* shd8) {
    const int t = threadIdx.x;
    #pragma unroll
    for (int o = 16; o > 0; o >>= 1) v += __shfl_xor_sync(0xffffffffu, v, o);
    const int warp = t >> 5, lane = t & 31;
    if (lane == 0) shd8[warp] = v;
    __syncthreads();
    if (warp == 0) {
        double x = (lane < 8) ? shd8[lane] : 0.0;
        #pragma unroll
        for (int o = 4; o > 0; o >>= 1) x += __shfl_xor_sync(0xffffffffu, x, o);
        if (lane == 0) shd8[0] = x;
    }
    __syncthreads();
    double r = shd8[0];
    __syncthreads();
    return r;
}

// ===================== normalize + bf16 split ==============================
__global__ void normalize_cb_kernel(const float* __restrict__ in) {
    __shared__ float sh[8];
    const int row = blockIdx.x, t = threadIdx.x;
    const float v = in[row * D_DIM + t];
    const float ss = block_reduce_sum256(v * v, sh);
    const float q = v / fmaxf(sqrtf(ss), 1e-12f);
    g_cbn[row * D_DIM + t] = q;
    const __nv_bfloat16 h = __float2bfloat16(q);
    g_cbh[row * D_DIM + t] = h;
    g_cbl[row * D_DIM + t] = __float2bfloat16(q - __bfloat162float(h));
    if (t == 0) g_counts[row] = 0;
}
__global__ void normalize_x_kernel(const float* __restrict__ in) {
    __shared__ float sh[8];
    const int row = blockIdx.x, t = threadIdx.x;
    const float v = in[row * D_DIM + t];
    const float ss = block_reduce_sum256(v * v, sh);
    const float q = v / fmaxf(sqrtf(ss), 1e-12f);
    g_xn[row * D_DIM + t] = q;
    const __nv_bfloat16 h = __float2bfloat16(q);
    g_xh[row * D_DIM + t] = h;
    g_xl[row * D_DIM + t] = __float2bfloat16(q - __bfloat162float(h));
}

// ===================== mma.sync split-bf16 GEMM ============================
// logits[m,n] = 20*(xh·cbh + xh·cbl + xl·cbh) - 20
// CTA 128x128, 8 warps (2M x 4N), warp tile 64x32, m16n8k16 HMMA,
// 24 double-buffered BK=32 chunks (3 phases x 8), 1 sync/iter.
#define SA 40   // padded smem row stride (bf16 units) -> conflict-free frags

__global__ __launch_bounds__(256)
void gemm_tc_kernel(float* __restrict__ C) {
    __shared__ __nv_bfloat16 As[2][128][SA];
    __shared__ __nv_bfloat16 Bs[2][128][SA];

    const int t = threadIdx.x;
    const int wid = t >> 5, lane = t & 31;
    const int g = lane >> 2, tig = lane & 3;
    const int warpM = wid & 1;        // 0..1  (64 rows each)
    const int warpN = wid >> 1;       // 0..3  (32 cols each)
    const int m0 = blockIdx.y << 7;
    const int n0 = blockIdx.x << 7;

    float acc[4][4][4];
    #pragma unroll
    for (int i = 0; i < 4; i++)
        #pragma unroll
        for (int j = 0; j < 4; j++)
            #pragma unroll
            for (int c = 0; c < 4; c++) acc[i][j][c] = 0.0f;

    const int lrow = t >> 1;          // 0..127
    const int lk   = (t & 1) << 4;    // 0 or 16

    uint4 ra0, ra1, rb0, rb1;
    {   // preload chunk 0 (phase hh, d0=0)
        const __nv_bfloat16* Ap = g_xh  + (size_t)(m0 + lrow) * D_DIM + lk;
        const __nv_bfloat16* Bp = g_cbh + (size_t)(n0 + lrow) * D_DIM + lk;
        ra0 = ((const uint4*)Ap)[0]; ra1 = ((const uint4*)Ap)[1];
        rb0 = ((const uint4*)Bp)[0]; rb1 = ((const uint4*)Bp)[1];
    }
    *(uint4*)&As[0][lrow][lk] = ra0; *(uint4*)&As[0][lrow][lk + 8] = ra1;
    *(uint4*)&Bs[0][lrow][lk] = rb0; *(uint4*)&Bs[0][lrow][lk + 8] = rb1;
    __syncthreads();

    #pragma unroll 1
    for (int kt = 0; kt < 24; kt++) {
        const int buf = kt & 1;
        if (kt < 23) {
            const int kn = kt + 1;
            const int phase = kn >> 3;          // 0:hh 1:h*l 2:l*h
            const int d0 = (kn & 7) << 5;       // 0..224
            const __nv_bfloat16* Asrc = (phase == 2) ? g_xl  : g_xh;
            const __nv_bfloat16* Bsrc = (phase == 1) ? g_cbl : g_cbh;
            const __nv_bfloat16* Ap = Asrc + (size_t)(m0 + lrow) * D_DIM + d0 + lk;
            const __nv_bfloat16* Bp = Bsrc + (size_t)(n0 + lrow) * D_DIM + d0 + lk;
            ra0 = ((const uint4*)Ap)[0]; ra1 = ((const uint4*)Ap)[1];
            rb0 = ((const uint4*)Bp)[0]; rb1 = ((const uint4*)Bp)[1];
        }

        #pragma unroll
        for (int k0 = 0; k0 < 32; k0 += 16) {
            uint32_t af[4][4], bf[4][2];
            #pragma unroll
            for (int mt = 0; mt < 4; mt++) {
                const int r0 = warpM * 64 + mt * 16 + g;
                af[mt][0] = *(const uint32_t*)&As[buf][r0]    [k0 + tig * 2];
                af[mt][1] = *(const uint32_t*)&As[buf][r0 + 8][k0 + tig * 2];
                af[mt][2] = *(const uint32_t*)&As[buf][r0]    [k0 + 8 + tig * 2];
                af[mt][3] = *(const uint32_t*)&As[buf][r0 + 8][k0 + 8 + tig * 2];
            }
            #pragma unroll
            for (int nt = 0; nt < 4; nt++) {
                const int c0 = warpN * 32 + nt * 8 + g;
                bf[nt][0] = *(const uint32_t*)&Bs[buf][c0][k0 + tig * 2];
                bf[nt][1] = *(const uint32_t*)&Bs[buf][c0][k0 + 8 + tig * 2];
            }
            #pragma unroll
            for (int mt = 0; mt < 4; mt++)
                #pragma unroll
                for (int nt = 0; nt < 4; nt++)
                    asm volatile(
                        "mma.sync.aligned.m16n8k16.row.col.f32.bf16.bf16.f32 "
                        "{%0,%1,%2,%3}, {%4,%5,%6,%7}, {%8,%9}, {%0,%1,%2,%3};"
                        : "+f"(acc[mt][nt][0]), "+f"(acc[mt][nt][1]),
                          "+f"(acc[mt][nt][2]), "+f"(acc[mt][nt][3])
                        : "r"(af[mt][0]), "r"(af[mt][1]), "r"(af[mt][2]), "r"(af[mt][3]),
                          "r"(bf[nt][0]), "r"(bf[nt][1]));
        }

        if (kt < 23) {
            const int nb = buf ^ 1;
            *(uint4*)&As[nb][lrow][lk] = ra0; *(uint4*)&As[nb][lrow][lk + 8] = ra1;
            *(uint4*)&Bs[nb][lrow][lk] = rb0; *(uint4*)&Bs[nb][lrow][lk + 8] = rb1;
            __syncthreads();
        }
    }

    // epilogue: scalar paired stores (C region is only 4B-aligned)
    #pragma unroll
    for (int mt = 0; mt < 4; mt++) {
        #pragma unroll
        for (int nt = 0; nt < 4; nt++) {
            const int r  = m0 + warpM * 64 + mt * 16 + g;
            const int cc = n0 + warpN * 32 + nt * 8 + tig * 2;
            float* p0 = C + (size_t)r * K_CB + cc;
            float* p1 = C + (size_t)(r + 8) * K_CB + cc;
            p0[0] = fmaf(20.0f, acc[mt][nt][0], -20.0f);
            p0[1] = fmaf(20.0f, acc[mt][nt][1], -20.0f);
            p1[0] = fmaf(20.0f, acc[mt][nt][2], -20.0f);
            p1[1] = fmaf(20.0f, acc[mt][nt][3], -20.0f);
        }
    }
}

// ===================== softmax / argmin / gather ===========================
#define MAX_CAND 64

__global__ __launch_bounds__(256)
void softmax_row_kernel(float* __restrict__ probs,
                        float* __restrict__ quant,
                        float* __restrict__ idx_out) {
    __shared__ float  xrow[256];
    __shared__ float  sh8[8];
    __shared__ double shd8[8];
    __shared__ int    cand[MAX_CAND];
    __shared__ double cdist[MAX_CAND];
    __shared__ int    ncand;
    __shared__ int    ridx_sh;

    const int n = blockIdx.x, t = threadIdx.x;
    float* row = probs + (size_t)n * K_CB;

    xrow[t] = g_xn[n * D_DIM + t];
    if (t == 0) ncand = 0;

    float lv[16];
    float best = -1e30f;
    #pragma unroll
    for (int i = 0; i < 16; i++) {
        lv[i] = row[t + (i << 8)];
        best = fmaxf(best, lv[i]);
    }
    __syncthreads();
    const float rmax = block_reduce_max256(best, sh8);

    const float thresh = rmax - 1e-3f;   // >> split-bf16 GEMM noise (~1e-4)
    #pragma unroll
    for (int i = 0; i < 16; i++) {
        if (lv[i] >= thresh) {
            const int p = atomicAdd(&ncand, 1);
            if (p < MAX_CAND) cand[p] = t + (i << 8);
        }
    }
    __syncthreads();
    const int nc = min(ncand, MAX_CAND);

    for (int c = 0; c < nc; c++) {
        const int k = cand[c];
        const double prod = (double)xrow[t] * (double)g_cbn[(size_t)k * D_DIM + t];
        const double s = block_reduce_sum256_d(prod, shd8);
        if (t == 0) cdist[c] = 2.0 - 2.0 * s;
    }
    __syncthreads();

    if (t == 0) {
        double dmin = 1e30;
        for (int c = 0; c < nc; c++) dmin = fmin(dmin, cdist[c]);
        int bi = 0x7fffffff;
        for (int c = 0; c < nc; c++)
            if (cdist[c] <= dmin + 4e-7) bi = min(bi, cand[c]);
        ridx_sh = bi;
    }

    float ssum = 0.0f;
    #pragma unroll
    for (int i = 0; i < 16; i++) {
        lv[i] = __expf(lv[i] - rmax);
        ssum += lv[i];
    }
    const float tot = block_reduce_sum256(ssum, sh8);
    const float inv = 1.0f / tot;
    #pragma unroll
    for (int i = 0; i < 16; i++) row[t + (i << 8)] = lv[i] * inv;

    const int ridx = ridx_sh;
    const float xv = xrow[t];
    const float cv = g_cbn[(size_t)ridx * D_DIM + t];
    quant[(size_t)n * D_DIM + t] = xv + (cv - xv);
    const float d = cv - xv;
    const float lp = block_reduce_sum256(d * d, sh8);
    if (t == 0) {
        g_loss_partial[n] = lp;
        atomicAdd(&g_counts[ridx], 1);
        idx_out[n] = (float)ridx;
    }
}

// ===================== finalize ============================================
__global__ void finalize_kernel(float* __restrict__ out_loss,
                                float* __restrict__ out_perp) {
    __shared__ float sh[8];
    const int t = threadIdx.x;
    float s = 0.0f;
    for (int i = t; i < N_ROWS; i += 256) s += g_loss_partial[i];
    const float tot = block_reduce_sum256(s, sh);

    float e = 0.0f;
    for (int i = t; i < K_CB; i += 256) {
        const float p = (float)g_counts[i] / (float)N_ROWS;
        e += p * logf(p + 1e-10f);
    }
    const float esum = block_reduce_sum256(e, sh);

    if (t == 0) {
        *out_loss = 0.25f * (tot / (float)((size_t)N_ROWS * D_DIM));
        *out_perp = expf(-esum);
    }
}

// ===========================================================================
extern "C" void kernel_launch(void* const* d_in, const int* in_sizes, int n_in,
                              void* d_out, int out_size) {
    const float* inputs   = (const float*)d_in[0];
    const float* codebook = (const float*)d_in[1];

    float* out       = (float*)d_out;
    float* out_loss  = out;
    float* out_quant = out + 1;
    float* out_probs = out_quant + (size_t)N_ROWS * D_DIM;
    float* out_perp  = out_probs + (size_t)N_ROWS * K_CB;
    float* out_idx   = out_perp + 1;

    normalize_cb_kernel<<<K_CB, 256>>>(codebook);
    normalize_x_kernel<<<N_ROWS, 256>>>(inputs);

    dim3 grid(K_CB / 128, N_ROWS / 128);   // (32, 128)
    gemm_tc_kernel<<<grid, 256>>>(out_probs);

    softmax_row_kernel<<<N_ROWS, 256>>>(out_probs, out_quant, out_idx);
    finalize_kernel<<<1, 256>>>(out_loss, out_perp);
}

// round 8
// speedup vs baseline: 2.4868x; 1.0710x over previous
#include <cuda_runtime.h>
#include <cuda_bf16.h>
#include <math.h>
#include <cstdint>

#define N_ROWS 16384
#define K_CB   4096
#define D_DIM  256

__device__ float g_xn[N_ROWS * D_DIM];
__device__ float g_cbn[K_CB * D_DIM];
__device__ __nv_bfloat16 g_xh[N_ROWS * D_DIM];
__device__ __nv_bfloat16 g_xl[N_ROWS * D_DIM];
__device__ __nv_bfloat16 g_cbh[K_CB * D_DIM];
__device__ __nv_bfloat16 g_cbl[K_CB * D_DIM];
__device__ float g_loss_partial[N_ROWS];
__device__ int   g_counts[K_CB];

__device__ __forceinline__ uint32_t smem_u32(const void* p) {
    uint32_t a;
    asm("{ .reg .u64 t; cvta.to.shared.u64 t, %1; cvt.u32.u64 %0, t; }" : "=r"(a) : "l"(p));
    return a;
}

// ===================== reductions ==========================================
__device__ __forceinline__ float block_reduce_sum256(float v, float* sh8) {
    const int t = threadIdx.x;
    #pragma unroll
    for (int o = 16; o > 0; o >>= 1) v += __shfl_xor_sync(0xffffffffu, v, o);
    const int warp = t >> 5, lane = t & 31;
    if (lane == 0) sh8[warp] = v;
    __syncthreads();
    if (warp == 0) {
        float x = (lane < 8) ? sh8[lane] : 0.0f;
        #pragma unroll
        for (int o = 4; o > 0; o >>= 1) x += __shfl_xor_sync(0xffffffffu, x, o);
        if (lane == 0) sh8[0] = x;
    }
    __syncthreads();
    float r = sh8[0];
    __syncthreads();
    return r;
}
__device__ __forceinline__ float block_reduce_max256(float v, float* sh8) {
    const int t = threadIdx.x;
    #pragma unroll
    for (int o = 16; o > 0; o >>= 1) v = fmaxf(v, __shfl_xor_sync(0xffffffffu, v, o));
    const int warp = t >> 5, lane = t & 31;
    if (lane == 0) sh8[warp] = v;
    __syncthreads();
    if (warp == 0) {
        float x = (lane < 8) ? sh8[lane] : -1e30f;
        #pragma unroll
        for (int o = 4; o > 0; o >>= 1) x = fmaxf(x, __shfl_xor_sync(0xffffffffu, x, o));
        if (lane == 0) sh8[0] = x;
    }
    __syncthreads();
    float r = sh8[0];
    __syncthreads();
    return r;
}
__device__ __forceinline__ double block_reduce_sum256_d(double v, double* shd8) {
    const int t = threadIdx.x;
    #pragma unroll
    for (int o = 16; o > 0; o >>= 1) v += __shfl_xor_sync(0xffffffffu, v, o);
    const int warp = t >> 5, lane = t & 31;
    if (lane == 0) shd8[warp] = v;
    __syncthreads();
    if (warp == 0) {
        double x = (lane < 8) ? shd8[lane] : 0.0;
        #pragma unroll
        for (int o = 4; o > 0; o >>= 1) x += __shfl_xor_sync(0xffffffffu, x, o);
        if (lane == 0) shd8[0] = x;
    }
    __syncthreads();
    double r = shd8[0];
    __syncthreads();
    return r;
}

// ===================== normalize + bf16 split ==============================
__global__ void normalize_cb_kernel(const float* __restrict__ in) {
    __shared__ float sh[8];
    const int row = blockIdx.x, t = threadIdx.x;
    const float v = in[row * D_DIM + t];
    const float ss = block_reduce_sum256(v * v, sh);
    const float q = v / fmaxf(sqrtf(ss), 1e-12f);
    g_cbn[row * D_DIM + t] = q;
    const __nv_bfloat16 h = __float2bfloat16(q);
    g_cbh[row * D_DIM + t] = h;
    g_cbl[row * D_DIM + t] = __float2bfloat16(q - __bfloat162float(h));
    if (t == 0) g_counts[row] = 0;
}
__global__ void normalize_x_kernel(const float* __restrict__ in) {
    __shared__ float sh[8];
    const int row = blockIdx.x, t = threadIdx.x;
    const float v = in[row * D_DIM + t];
    const float ss = block_reduce_sum256(v * v, sh);
    const float q = v / fmaxf(sqrtf(ss), 1e-12f);
    g_xn[row * D_DIM + t] = q;
    const __nv_bfloat16 h = __float2bfloat16(q);
    g_xh[row * D_DIM + t] = h;
    g_xl[row * D_DIM + t] = __float2bfloat16(q - __bfloat162float(h));
}

// ===================== mma.sync split-bf16 GEMM ============================
// logits[m,n] = 20*(xh·cbh + xh·cbl + xl·cbh) - 20
// CTA 128x128, 8 warps (2M x 4N), warp tile 64x32, m16n8k16 HMMA,
// fragments via ldmatrix.x4, 24 double-buffered BK=32 chunks, 1 sync/iter.
#define SA 40   // padded smem row stride (bf16) -> conflict-free LDSM phases

__global__ __launch_bounds__(256)
void gemm_tc_kernel(float* __restrict__ C) {
    __shared__ __nv_bfloat16 As[2][128][SA];
    __shared__ __nv_bfloat16 Bs[2][128][SA];

    const int t = threadIdx.x;
    const int wid = t >> 5, lane = t & 31;
    const int g = lane >> 2, tig = lane & 3;
    const int warpM = wid & 1;
    const int warpN = wid >> 1;
    const int m0 = blockIdx.y << 7;
    const int n0 = blockIdx.x << 7;

    // ldmatrix lane->row mapping: row = (lane&15), kofs = 8*(lane>>4)
    const int lsel = lane & 15;
    const int ksel = (lane >> 4) << 3;

    float acc[4][4][4];
    #pragma unroll
    for (int i = 0; i < 4; i++)
        #pragma unroll
        for (int j = 0; j < 4; j++)
            #pragma unroll
            for (int c = 0; c < 4; c++) acc[i][j][c] = 0.0f;

    const int lrow = t >> 1;
    const int lk   = (t & 1) << 4;

    uint4 ra0, ra1, rb0, rb1;
    {
        const __nv_bfloat16* Ap = g_xh  + (size_t)(m0 + lrow) * D_DIM + lk;
        const __nv_bfloat16* Bp = g_cbh + (size_t)(n0 + lrow) * D_DIM + lk;
        ra0 = ((const uint4*)Ap)[0]; ra1 = ((const uint4*)Ap)[1];
        rb0 = ((const uint4*)Bp)[0]; rb1 = ((const uint4*)Bp)[1];
    }
    *(uint4*)&As[0][lrow][lk] = ra0; *(uint4*)&As[0][lrow][lk + 8] = ra1;
    *(uint4*)&Bs[0][lrow][lk] = rb0; *(uint4*)&Bs[0][lrow][lk + 8] = rb1;
    __syncthreads();

    #pragma unroll 1
    for (int kt = 0; kt < 24; kt++) {
        const int buf = kt & 1;
        if (kt < 23) {
            const int kn = kt + 1;
            const int phase = kn >> 3;
            const int d0 = (kn & 7) << 5;
            const __nv_bfloat16* Asrc = (phase == 2) ? g_xl  : g_xh;
            const __nv_bfloat16* Bsrc = (phase == 1) ? g_cbl : g_cbh;
            const __nv_bfloat16* Ap = Asrc + (size_t)(m0 + lrow) * D_DIM + d0 + lk;
            const __nv_bfloat16* Bp = Bsrc + (size_t)(n0 + lrow) * D_DIM + d0 + lk;
            ra0 = ((const uint4*)Ap)[0]; ra1 = ((const uint4*)Ap)[1];
            rb0 = ((const uint4*)Bp)[0]; rb1 = ((const uint4*)Bp)[1];
        }

        #pragma unroll
        for (int k0 = 0; k0 < 32; k0 += 16) {
            uint32_t af[4][4], bf[4][2];
            #pragma unroll
            for (int mt = 0; mt < 4; mt++) {
                const uint32_t aaddr =
                    smem_u32(&As[buf][warpM * 64 + mt * 16 + lsel][k0 + ksel]);
                asm volatile(
                    "ldmatrix.sync.aligned.m8n8.x4.shared.b16 {%0,%1,%2,%3}, [%4];"
                    : "=r"(af[mt][0]), "=r"(af[mt][1]), "=r"(af[mt][2]), "=r"(af[mt][3])
                    : "r"(aaddr));
            }
            #pragma unroll
            for (int np = 0; np < 2; np++) {
                const uint32_t baddr =
                    smem_u32(&Bs[buf][warpN * 32 + np * 16 + lsel][k0 + ksel]);
                asm volatile(
                    "ldmatrix.sync.aligned.m8n8.x4.shared.b16 {%0,%1,%2,%3}, [%4];"
                    : "=r"(bf[2 * np][0]), "=r"(bf[2 * np + 1][0]),
                      "=r"(bf[2 * np][1]), "=r"(bf[2 * np + 1][1])
                    : "r"(baddr));
            }
            #pragma unroll
            for (int mt = 0; mt < 4; mt++)
                #pragma unroll
                for (int nt = 0; nt < 4; nt++)
                    asm volatile(
                        "mma.sync.aligned.m16n8k16.row.col.f32.bf16.bf16.f32 "
                        "{%0,%1,%2,%3}, {%4,%5,%6,%7}, {%8,%9}, {%0,%1,%2,%3};"
                        : "+f"(acc[mt][nt][0]), "+f"(acc[mt][nt][1]),
                          "+f"(acc[mt][nt][2]), "+f"(acc[mt][nt][3])
                        : "r"(af[mt][0]), "r"(af[mt][1]), "r"(af[mt][2]), "r"(af[mt][3]),
                          "r"(bf[nt][0]), "r"(bf[nt][1]));
        }

        if (kt < 23) {
            const int nb = buf ^ 1;
            *(uint4*)&As[nb][lrow][lk] = ra0; *(uint4*)&As[nb][lrow][lk + 8] = ra1;
            *(uint4*)&Bs[nb][lrow][lk] = rb0; *(uint4*)&Bs[nb][lrow][lk + 8] = rb1;
            __syncthreads();
        }
    }

    // epilogue: scalar paired stores (C region is only 4B-aligned)
    #pragma unroll
    for (int mt = 0; mt < 4; mt++) {
        #pragma unroll
        for (int nt = 0; nt < 4; nt++) {
            const int r  = m0 + warpM * 64 + mt * 16 + g;
            const int cc = n0 + warpN * 32 + nt * 8 + tig * 2;
            float* p0 = C + (size_t)r * K_CB + cc;
            float* p1 = C + (size_t)(r + 8) * K_CB + cc;
            p0[0] = fmaf(20.0f, acc[mt][nt][0], -20.0f);
            p0[1] = fmaf(20.0f, acc[mt][nt][1], -20.0f);
            p1[0] = fmaf(20.0f, acc[mt][nt][2], -20.0f);
            p1[1] = fmaf(20.0f, acc[mt][nt][3], -20.0f);
        }
    }
}

// ===================== softmax / argmin / gather ===========================
#define MAX_CAND 64

__global__ __launch_bounds__(256)
void softmax_row_kernel(float* __restrict__ probs,
                        float* __restrict__ quant,
                        float* __restrict__ idx_out) {
    __shared__ float  xrow[256];
    __shared__ float  sh8[8];
    __shared__ double shd8[8];
    __shared__ int    cand[MAX_CAND];
    __shared__ double cdist[MAX_CAND];
    __shared__ int    ncand;
    __shared__ int    ridx_sh;

    const int n = blockIdx.x, t = threadIdx.x;
    float* row = probs + (size_t)n * K_CB;

    xrow[t] = g_xn[n * D_DIM + t];
    if (t == 0) ncand = 0;

    float lv[16];
    float best = -1e30f;
    #pragma unroll
    for (int i = 0; i < 16; i++) {
        lv[i] = row[t + (i << 8)];
        best = fmaxf(best, lv[i]);
    }
    __syncthreads();
    const float rmax = block_reduce_max256(best, sh8);

    const float thresh = rmax - 1e-3f;
    #pragma unroll
    for (int i = 0; i < 16; i++) {
        if (lv[i] >= thresh) {
            const int p = atomicAdd(&ncand, 1);
            if (p < MAX_CAND) cand[p] = t + (i << 8);
        }
    }
    __syncthreads();
    const int nc = min(ncand, MAX_CAND);

    for (int c = 0; c < nc; c++) {
        const int k = cand[c];
        const double prod = (double)xrow[t] * (double)g_cbn[(size_t)k * D_DIM + t];
        const double s = block_reduce_sum256_d(prod, shd8);
        if (t == 0) cdist[c] = 2.0 - 2.0 * s;
    }
    __syncthreads();

    if (t == 0) {
        double dmin = 1e30;
        for (int c = 0; c < nc; c++) dmin = fmin(dmin, cdist[c]);
        int bi = 0x7fffffff;
        for (int c = 0; c < nc; c++)
            if (cdist[c] <= dmin + 4e-7) bi = min(bi, cand[c]);
        ridx_sh = bi;
    }

    float ssum = 0.0f;
    #pragma unroll
    for (int i = 0; i < 16; i++) {
        lv[i] = __expf(lv[i] - rmax);
        ssum += lv[i];
    }
    const float tot = block_reduce_sum256(ssum, sh8);
    const float inv = 1.0f / tot;
    #pragma unroll
    for (int i = 0; i < 16; i++) row[t + (i << 8)] = lv[i] * inv;

    const int ridx = ridx_sh;
    const float xv = xrow[t];
    const float cv = g_cbn[(size_t)ridx * D_DIM + t];
    quant[(size_t)n * D_DIM + t] = xv + (cv - xv);
    const float d = cv - xv;
    const float lp = block_reduce_sum256(d * d, sh8);
    if (t == 0) {
        g_loss_partial[n] = lp;
        atomicAdd(&g_counts[ridx], 1);
        idx_out[n] = (float)ridx;
    }
}

// ===================== finalize ============================================
__global__ void finalize_kernel(float* __restrict__ out_loss,
                                float* __restrict__ out_perp) {
    __shared__ float sh[8];
    const int t = threadIdx.x;
    float s = 0.0f;
    for (int i = t; i < N_ROWS; i += 256) s += g_loss_partial[i];
    const float tot = block_reduce_sum256(s, sh);

    float e = 0.0f;
    for (int i = t; i < K_CB; i += 256) {
        const float p = (float)g_counts[i] / (float)N_ROWS;
        e += p * logf(p + 1e-10f);
    }
    const float esum = block_reduce_sum256(e, sh);

    if (t == 0) {
        *out_loss = 0.25f * (tot / (float)((size_t)N_ROWS * D_DIM));
        *out_perp = expf(-esum);
    }
}

// ===========================================================================
extern "C" void kernel_launch(void* const* d_in, const int* in_sizes, int n_in,
                              void* d_out, int out_size) {
    const float* inputs   = (const float*)d_in[0];
    const float* codebook = (const float*)d_in[1];

    float* out       = (float*)d_out;
    float* out_loss  = out;
    float* out_quant = out + 1;
    float* out_probs = out_quant + (size_t)N_ROWS * D_DIM;
    float* out_perp  = out_probs + (size_t)N_ROWS * K_CB;
    float* out_idx   = out_perp + 1;

    normalize_cb_kernel<<<K_CB, 256>>>(codebook);
    normalize_x_kernel<<<N_ROWS, 256>>>(inputs);

    dim3 grid(K_CB / 128, N_ROWS / 128);   // (32, 128)
    gemm_tc_kernel<<<grid, 256>>>(out_probs);

    softmax_row_kernel<<<N_ROWS, 256>>>(out_probs, out_quant, out_idx);
    finalize_kernel<<<1, 256>>>(out_loss, out_perp);
}

// round 9
// speedup vs baseline: 2.5910x; 1.0419x over previous
#include <cuda_runtime.h>
#include <cuda_bf16.h>
#include <math.h>
#include <cstdint>

#define N_ROWS 16384
#define K_CB   4096
#define D_DIM  256

__device__ float g_xn[N_ROWS * D_DIM];
__device__ float g_cbn[K_CB * D_DIM];
__device__ __nv_bfloat16 g_xh[N_ROWS * D_DIM];
__device__ __nv_bfloat16 g_xl[N_ROWS * D_DIM];
__device__ __nv_bfloat16 g_cbh[K_CB * D_DIM];
__device__ __nv_bfloat16 g_cbl[K_CB * D_DIM];
__device__ float g_loss_partial[N_ROWS];
__device__ int   g_counts[K_CB];

__device__ __forceinline__ uint32_t smem_u32(const void* p) {
    uint32_t a;
    asm("{ .reg .u64 t; cvta.to.shared.u64 t, %1; cvt.u32.u64 %0, t; }" : "=r"(a) : "l"(p));
    return a;
}

// ===================== reductions ==========================================
__device__ __forceinline__ float block_reduce_sum256(float v, float* sh8) {
    const int t = threadIdx.x;
    #pragma unroll
    for (int o = 16; o > 0; o >>= 1) v += __shfl_xor_sync(0xffffffffu, v, o);
    const int warp = t >> 5, lane = t & 31;
    if (lane == 0) sh8[warp] = v;
    __syncthreads();
    if (warp == 0) {
        float x = (lane < 8) ? sh8[lane] : 0.0f;
        #pragma unroll
        for (int o = 4; o > 0; o >>= 1) x += __shfl_xor_sync(0xffffffffu, x, o);
        if (lane == 0) sh8[0] = x;
    }
    __syncthreads();
    float r = sh8[0];
    __syncthreads();
    return r;
}
__device__ __forceinline__ float block_reduce_max256(float v, float* sh8) {
    const int t = threadIdx.x;
    #pragma unroll
    for (int o = 16; o > 0; o >>= 1) v = fmaxf(v, __shfl_xor_sync(0xffffffffu, v, o));
    const int warp = t >> 5, lane = t & 31;
    if (lane == 0) sh8[warp] = v;
    __syncthreads();
    if (warp == 0) {
        float x = (lane < 8) ? sh8[lane] : -1e30f;
        #pragma unroll
        for (int o = 4; o > 0; o >>= 1) x = fmaxf(x, __shfl_xor_sync(0xffffffffu, x, o));
        if (lane == 0) sh8[0] = x;
    }
    __syncthreads();
    float r = sh8[0];
    __syncthreads();
    return r;
}
__device__ __forceinline__ double block_reduce_sum256_d(double v, double* shd8) {
    const int t = threadIdx.x;
    #pragma unroll
    for (int o = 16; o > 0; o >>= 1) v += __shfl_xor_sync(0xffffffffu, v, o);
    const int warp = t >> 5, lane = t & 31;
    if (lane == 0) shd8[warp] = v;
    __syncthreads();
    if (warp == 0) {
        double x = (lane < 8) ? shd8[lane] : 0.0;
        #pragma unroll
        for (int o = 4; o > 0; o >>= 1) x += __shfl_xor_sync(0xffffffffu, x, o);
        if (lane == 0) shd8[0] = x;
    }
    __syncthreads();
    double r = shd8[0];
    __syncthreads();
    return r;
}

// ===================== normalize + bf16 split ==============================
__global__ void normalize_cb_kernel(const float* __restrict__ in) {
    __shared__ float sh[8];
    const int row = blockIdx.x, t = threadIdx.x;
    const float v = in[row * D_DIM + t];
    const float ss = block_reduce_sum256(v * v, sh);
    const float q = v / fmaxf(sqrtf(ss), 1e-12f);
    g_cbn[row * D_DIM + t] = q;
    const __nv_bfloat16 h = __float2bfloat16(q);
    g_cbh[row * D_DIM + t] = h;
    g_cbl[row * D_DIM + t] = __float2bfloat16(q - __bfloat162float(h));
    if (t == 0) g_counts[row] = 0;
}
__global__ void normalize_x_kernel(const float* __restrict__ in) {
    __shared__ float sh[8];
    const int row = blockIdx.x, t = threadIdx.x;
    const float v = in[row * D_DIM + t];
    const float ss = block_reduce_sum256(v * v, sh);
    const float q = v / fmaxf(sqrtf(ss), 1e-12f);
    g_xn[row * D_DIM + t] = q;
    const __nv_bfloat16 h = __float2bfloat16(q);
    g_xh[row * D_DIM + t] = h;
    g_xl[row * D_DIM + t] = __float2bfloat16(q - __bfloat162float(h));
}

// ===================== cp.async pipelined split-bf16 GEMM ==================
// logits[m,n] = 20*(xh·cbh + xh·cbl + xl·cbh) - 20
// CTA 128x256, 8 warps (2M x 4N), warp tile 64x64, 3-stage cp.async ring,
// 24 BK=32 chunks (3 phases x 8). SA=40 bf16 row stride (conflict-free).
#define SA 40
#define A_STAGE_B (128 * SA * 2)          // 10240
#define B_STAGE_B (256 * SA * 2)          // 20480
#define STAGE_B   (A_STAGE_B + B_STAGE_B) // 30720
#define GEMM_SMEM (3 * STAGE_B)           // 92160

__device__ __forceinline__ void cp16(uint32_t saddr, const void* gptr) {
    asm volatile("cp.async.cg.shared.global [%0], [%1], 16;"
                 :: "r"(saddr), "l"(__cvta_generic_to_global(gptr)));
}

__global__ __launch_bounds__(256, 1)
void gemm_tc_kernel(float* __restrict__ C) {
    extern __shared__ char sm[];
    const uint32_t sbase = smem_u32(sm);

    const int t = threadIdx.x;
    const int wid = t >> 5, lane = t & 31;
    const int g = lane >> 2, tig = lane & 3;
    const int warpM = wid & 1;
    const int warpN = wid >> 1;
    const int m0 = blockIdx.y << 7;
    const int n0 = blockIdx.x << 8;

    const int lsel = lane & 15;
    const int ksel = (lane >> 4) << 3;

    float acc[4][8][4];
    #pragma unroll
    for (int i = 0; i < 4; i++)
        #pragma unroll
        for (int j = 0; j < 8; j++)
            #pragma unroll
            for (int c = 0; c < 4; c++) acc[i][j][c] = 0.0f;

    // loader chunk mapping
    const int arow = t >> 2, asub = t & 3;         // A: 2 chunks (rows t>>2, 64+)
    // A has 512 16B-chunks: c = t, t+256 -> rows c>>2
    // B has 1024: c = t + j*256

    auto issue_stage = [&](int stage, int kt) {
        const int phase = kt >> 3;
        const int d0 = (kt & 7) << 5;
        const __nv_bfloat16* Asrc = (phase == 2) ? g_xl  : g_xh;
        const __nv_bfloat16* Bsrc = (phase == 1) ? g_cbl : g_cbh;
        const uint32_t sa = sbase + stage * STAGE_B;
        const uint32_t sb = sa + A_STAGE_B;
        #pragma unroll
        for (int j = 0; j < 2; j++) {
            const int c = t + (j << 8);
            const int row = c >> 2, sub = c & 3;
            cp16(sa + row * (SA * 2) + sub * 16,
                 Asrc + (size_t)(m0 + row) * D_DIM + d0 + sub * 8);
        }
        #pragma unroll
        for (int j = 0; j < 4; j++) {
            const int c = t + (j << 8);
            const int row = c >> 2, sub = c & 3;
            cp16(sb + row * (SA * 2) + sub * 16,
                 Bsrc + (size_t)(n0 + row) * D_DIM + d0 + sub * 8);
        }
        asm volatile("cp.async.commit_group;");
    };

    issue_stage(0, 0);
    issue_stage(1, 1);

    #pragma unroll 1
    for (int kt = 0; kt < 24; kt++) {
        if (kt < 23) asm volatile("cp.async.wait_group 1;");
        else         asm volatile("cp.async.wait_group 0;");
        __syncthreads();

        const int stage = kt - (kt / 3) * 3;
        const uint32_t sa = sbase + stage * STAGE_B;
        const uint32_t sb = sa + A_STAGE_B;

        #pragma unroll
        for (int k0 = 0; k0 < 32; k0 += 16) {
            uint32_t af[4][4], bf[8][2];
            #pragma unroll
            for (int mt = 0; mt < 4; mt++) {
                const uint32_t aaddr = sa
                    + (warpM * 64 + mt * 16 + lsel) * (SA * 2) + (k0 + ksel) * 2;
                asm volatile(
                    "ldmatrix.sync.aligned.m8n8.x4.shared.b16 {%0,%1,%2,%3}, [%4];"
                    : "=r"(af[mt][0]), "=r"(af[mt][1]), "=r"(af[mt][2]), "=r"(af[mt][3])
                    : "r"(aaddr));
            }
            #pragma unroll
            for (int np = 0; np < 4; np++) {
                const uint32_t baddr = sb
                    + (warpN * 64 + np * 16 + lsel) * (SA * 2) + (k0 + ksel) * 2;
                asm volatile(
                    "ldmatrix.sync.aligned.m8n8.x4.shared.b16 {%0,%1,%2,%3}, [%4];"
                    : "=r"(bf[2 * np][0]), "=r"(bf[2 * np + 1][0]),
                      "=r"(bf[2 * np][1]), "=r"(bf[2 * np + 1][1])
                    : "r"(baddr));
            }
            #pragma unroll
            for (int mt = 0; mt < 4; mt++)
                #pragma unroll
                for (int nt = 0; nt < 8; nt++)
                    asm volatile(
                        "mma.sync.aligned.m16n8k16.row.col.f32.bf16.bf16.f32 "
                        "{%0,%1,%2,%3}, {%4,%5,%6,%7}, {%8,%9}, {%0,%1,%2,%3};"
                        : "+f"(acc[mt][nt][0]), "+f"(acc[mt][nt][1]),
                          "+f"(acc[mt][nt][2]), "+f"(acc[mt][nt][3])
                        : "r"(af[mt][0]), "r"(af[mt][1]), "r"(af[mt][2]), "r"(af[mt][3]),
                          "r"(bf[nt][0]), "r"(bf[nt][1]));
        }

        if (kt < 22) {
            __syncthreads();
            const int ns = (kt + 2) - ((kt + 2) / 3) * 3;
            issue_stage(ns, kt + 2);
        }
    }

    // epilogue: scalar paired stores (C region is only 4B-aligned)
    #pragma unroll
    for (int mt = 0; mt < 4; mt++) {
        #pragma unroll
        for (int nt = 0; nt < 8; nt++) {
            const int r  = m0 + warpM * 64 + mt * 16 + g;
            const int cc = n0 + warpN * 64 + nt * 8 + tig * 2;
            float* p0 = C + (size_t)r * K_CB + cc;
            float* p1 = C + (size_t)(r + 8) * K_CB + cc;
            p0[0] = fmaf(20.0f, acc[mt][nt][0], -20.0f);
            p0[1] = fmaf(20.0f, acc[mt][nt][1], -20.0f);
            p1[0] = fmaf(20.0f, acc[mt][nt][2], -20.0f);
            p1[1] = fmaf(20.0f, acc[mt][nt][3], -20.0f);
        }
    }
    (void)arow; (void)asub;
}

// ===================== softmax / argmin / gather ===========================
#define MAX_CAND 64

__global__ __launch_bounds__(256)
void softmax_row_kernel(float* __restrict__ probs,
                        float* __restrict__ quant,
                        float* __restrict__ idx_out) {
    __shared__ float  xrow[256];
    __shared__ float  sh8[8];
    __shared__ double shd8[8];
    __shared__ int    cand[MAX_CAND];
    __shared__ double cdist[MAX_CAND];
    __shared__ int    ncand;
    __shared__ int    ridx_sh;

    const int n = blockIdx.x, t = threadIdx.x;
    float* row = probs + (size_t)n * K_CB;

    xrow[t] = g_xn[n * D_DIM + t];
    if (t == 0) ncand = 0;

    float lv[16];
    float best = -1e30f;
    #pragma unroll
    for (int i = 0; i < 16; i++) {
        lv[i] = row[t + (i << 8)];
        best = fmaxf(best, lv[i]);
    }
    __syncthreads();
    const float rmax = block_reduce_max256(best, sh8);

    const float thresh = rmax - 1e-3f;
    #pragma unroll
    for (int i = 0; i < 16; i++) {
        if (lv[i] >= thresh) {
            const int p = atomicAdd(&ncand, 1);
            if (p < MAX_CAND) cand[p] = t + (i << 8);
        }
    }
    __syncthreads();
    const int nc = min(ncand, MAX_CAND);

    for (int c = 0; c < nc; c++) {
        const int k = cand[c];
        const double prod = (double)xrow[t] * (double)g_cbn[(size_t)k * D_DIM + t];
        const double s = block_reduce_sum256_d(prod, shd8);
        if (t == 0) cdist[c] = 2.0 - 2.0 * s;
    }
    __syncthreads();

    if (t == 0) {
        double dmin = 1e30;
        for (int c = 0; c < nc; c++) dmin = fmin(dmin, cdist[c]);
        int bi = 0x7fffffff;
        for (int c = 0; c < nc; c++)
            if (cdist[c] <= dmin + 4e-7) bi = min(bi, cand[c]);
        ridx_sh = bi;
    }

    float ssum = 0.0f;
    #pragma unroll
    for (int i = 0; i < 16; i++) {
        lv[i] = __expf(lv[i] - rmax);
        ssum += lv[i];
    }
    const float tot = block_reduce_sum256(ssum, sh8);
    const float inv = 1.0f / tot;
    #pragma unroll
    for (int i = 0; i < 16; i++) row[t + (i << 8)] = lv[i] * inv;

    const int ridx = ridx_sh;
    const float xv = xrow[t];
    const float cv = g_cbn[(size_t)ridx * D_DIM + t];
    quant[(size_t)n * D_DIM + t] = xv + (cv - xv);
    const float d = cv - xv;
    const float lp = block_reduce_sum256(d * d, sh8);
    if (t == 0) {
        g_loss_partial[n] = lp;
        atomicAdd(&g_counts[ridx], 1);
        idx_out[n] = (float)ridx;
    }
}

// ===================== finalize ============================================
__global__ void finalize_kernel(float* __restrict__ out_loss,
                                float* __restrict__ out_perp) {
    __shared__ float sh[8];
    const int t = threadIdx.x;
    float s = 0.0f;
    for (int i = t; i < N_ROWS; i += 256) s += g_loss_partial[i];
    const float tot = block_reduce_sum256(s, sh);

    float e = 0.0f;
    for (int i = t; i < K_CB; i += 256) {
        const float p = (float)g_counts[i] / (float)N_ROWS;
        e += p * logf(p + 1e-10f);
    }
    const float esum = block_reduce_sum256(e, sh);

    if (t == 0) {
        *out_loss = 0.25f * (tot / (float)((size_t)N_ROWS * D_DIM));
        *out_perp = expf(-esum);
    }
}

// ===========================================================================
extern "C" void kernel_launch(void* const* d_in, const int* in_sizes, int n_in,
                              void* d_out, int out_size) {
    const float* inputs   = (const float*)d_in[0];
    const float* codebook = (const float*)d_in[1];

    float* out       = (float*)d_out;
    float* out_loss  = out;
    float* out_quant = out + 1;
    float* out_probs = out_quant + (size_t)N_ROWS * D_DIM;
    float* out_perp  = out_probs + (size_t)N_ROWS * K_CB;
    float* out_idx   = out_perp + 1;

    cudaFuncSetAttribute(gemm_tc_kernel,
                         cudaFuncAttributeMaxDynamicSharedMemorySize, GEMM_SMEM);

    normalize_cb_kernel<<<K_CB, 256>>>(codebook);
    normalize_x_kernel<<<N_ROWS, 256>>>(inputs);

    dim3 grid(K_CB / 256, N_ROWS / 128);   // (16, 128)
    gemm_tc_kernel<<<grid, 256, GEMM_SMEM>>>(out_probs);

    softmax_row_kernel<<<N_ROWS, 256>>>(out_probs, out_quant, out_idx);
    finalize_kernel<<<1, 256>>>(out_loss, out_perp);
}